// round 1
// baseline (speedup 1.0000x reference)
#include <cuda_runtime.h>
#include <math.h>

#define T_LEN 131072
#define NS 64
#define MD 8
#define NCHUNK 592   // 4 * 148 SMs
#define CLEN 222     // ceil((T_LEN-1)/NCHUNK); 592*222 >= 131071

// ---- scratch (static device globals; no runtime allocation) ----
__device__ float g_w[(size_t)T_LEN * NS];     // normalized emission weights exp(e - max)
__device__ float g_maxlog[T_LEN];             // per-step emission log max
__device__ float g_loglam[NS * MD];
__device__ float g_lamsum[NS];
__device__ float g_Alin[NS * NS];             // exp(log_transition)
__device__ float g_M[(size_t)NCHUNK * NS * NS]; // chunk transfer matrices
__device__ float g_S[NCHUNK];                 // chunk log-scale sums
__device__ unsigned int g_hist[32];           // histogram of x values (for exact lgamma sum)

// ============================================================
// Pass -1: tiny setup (precompute log lambdas, row sums, linear A, zero hist)
// ============================================================
__global__ void setup_kernel(const float* __restrict__ lambdas,
                             const float* __restrict__ log_transition) {
    int tid = threadIdx.x;
    for (int idx = tid; idx < NS * MD; idx += blockDim.x)
        g_loglam[idx] = logf(lambdas[idx]);
    if (tid < NS) {
        float s = 0.f;
        #pragma unroll
        for (int m = 0; m < MD; m++) s += lambdas[tid * MD + m];
        g_lamsum[tid] = s;
    }
    for (int idx = tid; idx < NS * NS; idx += blockDim.x)
        g_Alin[idx] = expf(log_transition[idx]);
    if (tid < 32) g_hist[tid] = 0u;
}

// ============================================================
// Pass 0: per-step emission weights w[t,i] = exp(e[t,i] - max_i e[t,i]),
//         maxlog[t] = max_i e[t,i]; histogram of x for lgamma term.
//         One warp per timestep, lane handles states {lane, lane+32}.
// ============================================================
__global__ void __launch_bounds__(256) pass0_kernel(const int* __restrict__ x) {
    __shared__ float sll[NS * MD];
    __shared__ float slam[NS];
    __shared__ unsigned int shist[32];
    int tid = threadIdx.x;
    for (int idx = tid; idx < NS * MD; idx += blockDim.x) sll[idx] = g_loglam[idx];
    if (tid < NS) slam[tid] = g_lamsum[tid];
    if (tid < 32) shist[tid] = 0u;
    __syncthreads();

    int warp = tid >> 5, lane = tid & 31;
    int t = blockIdx.x * 8 + warp;

    int4 xa = *(const int4*)&x[(size_t)t * MD];
    int4 xb = *(const int4*)&x[(size_t)t * MD + 4];
    int xv[8] = {xa.x, xa.y, xa.z, xa.w, xb.x, xb.y, xb.z, xb.w};
    if (lane < 8) atomicAdd(&shist[xv[lane] & 31], 1u);

    float e0 = -slam[lane], e1 = -slam[lane + 32];
    #pragma unroll
    for (int m = 0; m < 8; m++) {
        float xm = (float)xv[m];
        e0 = fmaf(xm, sll[lane * MD + m], e0);
        e1 = fmaf(xm, sll[(lane + 32) * MD + m], e1);
    }
    float mx = fmaxf(e0, e1);
    #pragma unroll
    for (int o = 16; o > 0; o >>= 1)
        mx = fmaxf(mx, __shfl_xor_sync(0xffffffffu, mx, o));
    g_w[(size_t)t * NS + lane]      = expf(e0 - mx);
    g_w[(size_t)t * NS + lane + 32] = expf(e1 - mx);
    if (lane == 0) g_maxlog[t] = mx;

    __syncthreads();
    if (tid < 32 && shist[tid]) atomicAdd(&g_hist[tid], shist[tid]);
}

// ============================================================
// Pass 1: per-chunk 64x64 transfer matrix.
//   M <- diag(w_t * pending_inv) * (A @ M), lazy renormalization.
//   128 threads, each owns a 4x8 output tile. Single in-place M buffer
//   (reads complete before the post-loop barrier, then overwrite).
// ============================================================
__global__ void __launch_bounds__(128) pass1_kernel() {
    __shared__ float sAT[NS * NS];   // A transposed: sAT[k*64 + i] = A[i][k]
    __shared__ float sM[NS * NS];    // current chunk matrix (row-major [i][j])
    __shared__ float swb[2][NS];     // double-buffered emission weights (inv folded)
    __shared__ float wmax[4];

    int tid = threadIdx.x;
    int c = blockIdx.x;
    int t0 = 1 + c * CLEN;
    int nsteps = T_LEN - t0;
    if (nsteps > CLEN) nsteps = CLEN;
    if (nsteps < 0) nsteps = 0;

    int i0 = (tid >> 3) << 2;   // 4 output rows
    int j0 = (tid & 7) << 3;    // 8 output cols

    for (int idx = tid; idx < NS * NS; idx += 128) {
        int i = idx >> 6, k = idx & 63;
        sAT[k * NS + i] = g_Alin[idx];
        sM[idx] = (i == k) ? 1.f : 0.f;
    }
    if (tid < NS) swb[0][tid] = (nsteps > 0) ? g_w[(size_t)t0 * NS + tid] : 0.f;
    float S = 0.f;
    __syncthreads();

    float acc[4][8];
    #pragma unroll
    for (int di = 0; di < 4; di++)
        #pragma unroll
        for (int dj = 0; dj < 8; dj++) acc[di][dj] = 0.f;

    int p = 0;
    for (int step = 0; step < nsteps; step++) {
        int t = t0 + step;
        bool last = (step == nsteps - 1);
        // prefetch next step's emission weights + this step's maxlog (latency hidden by FMA loop)
        float w_pref = 0.f;
        if (tid < NS && !last) w_pref = g_w[(size_t)(t + 1) * NS + tid];
        float ml = (tid == 0) ? g_maxlog[t] : 0.f;

        #pragma unroll
        for (int di = 0; di < 4; di++)
            #pragma unroll
            for (int dj = 0; dj < 8; dj++) acc[di][dj] = 0.f;

        #pragma unroll 8
        for (int k = 0; k < NS; k++) {
            float4 a  = *(const float4*)&sAT[k * NS + i0];
            float4 m0 = *(const float4*)&sM[k * NS + j0];
            float4 m1 = *(const float4*)&sM[k * NS + j0 + 4];
            float av[4] = {a.x, a.y, a.z, a.w};
            float mv[8] = {m0.x, m0.y, m0.z, m0.w, m1.x, m1.y, m1.z, m1.w};
            #pragma unroll
            for (int di = 0; di < 4; di++)
                #pragma unroll
                for (int dj = 0; dj < 8; dj++)
                    acc[di][dj] = fmaf(av[di], mv[dj], acc[di][dj]);
        }
        __syncthreads();   // all reads of sM done -> safe to overwrite in place

        float lmax = 0.f;
        #pragma unroll
        for (int di = 0; di < 4; di++) {
            float wv = swb[p][i0 + di];
            #pragma unroll
            for (int dj = 0; dj < 8; dj++) {
                float v = acc[di][dj] * wv;
                acc[di][dj] = v;
                lmax = fmaxf(lmax, v);
            }
            *(float4*)&sM[(i0 + di) * NS + j0] =
                make_float4(acc[di][0], acc[di][1], acc[di][2], acc[di][3]);
            *(float4*)&sM[(i0 + di) * NS + j0 + 4] =
                make_float4(acc[di][4], acc[di][5], acc[di][6], acc[di][7]);
        }
        #pragma unroll
        for (int o = 16; o > 0; o >>= 1)
            lmax = fmaxf(lmax, __shfl_xor_sync(0xffffffffu, lmax, o));
        if ((tid & 31) == 0) wmax[tid >> 5] = lmax;
        __syncthreads();

        float s = fmaxf(fmaxf(wmax[0], wmax[1]), fmaxf(wmax[2], wmax[3]));
        s = fmaxf(s, 1e-35f);
        if (!last) {
            float inv = 1.f / s;
            if (tid < NS) swb[p ^ 1][tid] = w_pref * inv;   // fold normalization into next weights
            if (tid == 0) S += ml + logf(s);
        } else {
            if (tid == 0) S += ml;   // final matrix stays un-normalized; pass 2 absorbs it
        }
        p ^= 1;
    }

    // write out chunk matrix straight from registers
    float* dst = &g_M[(size_t)c * NS * NS];
    if (nsteps > 0) {
        #pragma unroll
        for (int di = 0; di < 4; di++) {
            *(float4*)&dst[(i0 + di) * NS + j0] =
                make_float4(acc[di][0], acc[di][1], acc[di][2], acc[di][3]);
            *(float4*)&dst[(i0 + di) * NS + j0 + 4] =
                make_float4(acc[di][4], acc[di][5], acc[di][6], acc[di][7]);
        }
    } else {
        #pragma unroll
        for (int di = 0; di < 4; di++)
            #pragma unroll
            for (int dj = 0; dj < 8; dj++)
                dst[(i0 + di) * NS + j0 + dj] = ((i0 + di) == (j0 + dj)) ? 1.f : 0.f;
    }
    if (tid == 0) g_S[c] = S;
}

// ============================================================
// Pass 2: sequential combine of chunk matrices (matvec), one block,
//         register double-buffered prefetch of the next chunk matrix.
// ============================================================
__global__ void __launch_bounds__(256) pass2_kernel(const int* __restrict__ x,
                                                    const float* __restrict__ priors,
                                                    float* __restrict__ out) {
    __shared__ float alpha[NS];
    __shared__ float part[256];
    __shared__ float anew[NS];
    __shared__ float evec[NS];
    __shared__ float sred;
    int tid = threadIdx.x;
    int i = tid & 63, q = tid >> 6;   // q selects k-range [16q, 16q+16)

    // alpha0 = exp(em[0] + prior - m0) (lgamma excluded; added at end)
    if (tid < NS) {
        float e = priors[tid] - g_lamsum[tid];
        #pragma unroll
        for (int m = 0; m < MD; m++)
            e = fmaf((float)x[m], g_loglam[tid * MD + m], e);
        evec[tid] = e;
    }
    __syncthreads();
    if (tid == 0) {
        float mx = evec[0];
        for (int k = 1; k < NS; k++) mx = fmaxf(mx, evec[k]);
        sred = mx;
    }
    __syncthreads();
    float m0 = sred;
    if (tid < NS) alpha[tid] = expf(evec[tid] - m0);
    double logscale = (double)m0;   // thread 0's copy is authoritative
    __syncthreads();

    float4 buf[2][4];
    {
        const float4* src = (const float4*)&g_M[(size_t)i * NS + q * 16];
        #pragma unroll
        for (int r = 0; r < 4; r++) buf[0][r] = src[r];
    }
    int pp = 0;
    for (int c = 0; c < NCHUNK; c++) {
        if (c + 1 < NCHUNK) {   // prefetch next chunk; latency hides under reduce/syncs
            const float4* src =
                (const float4*)&g_M[(size_t)(c + 1) * NS * NS + i * NS + q * 16];
            #pragma unroll
            for (int r = 0; r < 4; r++) buf[pp ^ 1][r] = src[r];
        }
        float partial = 0.f;
        #pragma unroll
        for (int r = 0; r < 4; r++) {
            float4 v = buf[pp][r];
            int kb = q * 16 + r * 4;
            partial = fmaf(v.x, alpha[kb], partial);
            partial = fmaf(v.y, alpha[kb + 1], partial);
            partial = fmaf(v.z, alpha[kb + 2], partial);
            partial = fmaf(v.w, alpha[kb + 3], partial);
        }
        part[tid] = partial;
        __syncthreads();
        if (tid < NS)
            anew[tid] = part[tid] + part[tid + 64] + part[tid + 128] + part[tid + 192];
        __syncthreads();
        if (tid == 0) {
            float s = anew[0];
            for (int k = 1; k < NS; k++) s = fmaxf(s, anew[k]);
            s = fmaxf(s, 1e-35f);
            sred = s;
            logscale += (double)g_S[c] + log((double)s);
        }
        __syncthreads();
        float sv = sred;
        if (tid < NS) alpha[tid] = anew[tid] / sv;
        __syncthreads();
        pp ^= 1;
    }

    if (tid == 0) {
        double sum = 0.0;
        for (int k = 0; k < NS; k++) sum += (double)alpha[k];
        double lgam = 0.0;
        for (int b = 0; b < 32; b++) {
            unsigned int cnt = g_hist[b];
            if (cnt) lgam += (double)cnt * lgamma((double)b + 1.0);
        }
        out[0] = (float)(logscale + log(sum) - lgam);
    }
}

// ============================================================
extern "C" void kernel_launch(void* const* d_in, const int* in_sizes, int n_in,
                              void* d_out, int out_size) {
    const int*   x              = (const int*)d_in[0];
    const float* lambdas        = (const float*)d_in[1];
    const float* log_transition = (const float*)d_in[2];
    const float* priors         = (const float*)d_in[3];
    float* out = (float*)d_out;

    setup_kernel<<<1, 256>>>(lambdas, log_transition);
    pass0_kernel<<<T_LEN / 8, 256>>>(x);
    pass1_kernel<<<NCHUNK, 128>>>();
    pass2_kernel<<<1, 256>>>(x, priors, out);
}

// round 3
// speedup vs baseline: 6.9376x; 6.9376x over previous
#include <cuda_runtime.h>
#include <cuda_bf16.h>
#include <math.h>
#include <stdint.h>

#define T_LEN 131072
#define NS 64
#define MD 8
#define NCH1 444          // pass1 chunks: 3 per SM * 148
#define NCH3 148          // after triple-combine
#define L_BASE 295        // 131071 = 444*295 + 91
#define L_REM 91          // first 91 chunks have length 296

// ---- static device scratch ----
__device__ float g_w[(size_t)T_LEN * NS];
__device__ float g_maxlog[T_LEN];
__device__ float g_loglam[NS * MD];
__device__ float g_lamsum[NS];
__device__ float g_Alin[NS * NS];
__device__ float g_M1[(size_t)NCH1 * NS * NS];   // natural layout: [c][i][j]
__device__ float g_M3[(size_t)NCH3 * NS * NS];   // P-layout: [c][j][i] = R[i][j]
__device__ float g_S1[NCH1];
__device__ float g_S3[NCH3];
__device__ unsigned int g_hist[32];

// ================= helpers =================
__device__ __forceinline__ uint32_t smem_u32(const void* p) {
    uint32_t a;
    asm("{ .reg .u64 t; cvta.to.shared.u64 t, %1; cvt.u32.u64 %0, t; }" : "=r"(a) : "l"(p));
    return a;
}
#define SW128(o) ((uint32_t)(o) ^ ((((uint32_t)(o)) >> 3) & 0x70u))
#define CVT_BF2(r, lo, hi) asm("cvt.rn.bf16x2.f32 %0, %1, %2;" : "=r"(r) : "f"(hi), "f"(lo))
#define STS32(v, a) asm volatile("st.shared.b32 [%0], %1;" :: "r"(a), "r"(v) : "memory")
#define LDSM_X4(r0, r1, r2, r3, a) \
    asm volatile("ldmatrix.sync.aligned.m8n8.x4.shared.b16 {%0,%1,%2,%3}, [%4];" \
                 : "=r"(r0), "=r"(r1), "=r"(r2), "=r"(r3) : "r"(a))
#define LDSM_X4_T(r0, r1, r2, r3, a) \
    asm volatile("ldmatrix.sync.aligned.m8n8.x4.trans.shared.b16 {%0,%1,%2,%3}, [%4];" \
                 : "=r"(r0), "=r"(r1), "=r"(r2), "=r"(r3) : "r"(a))
#define MMA_BF16(d, a, b0, b1) \
    asm volatile("mma.sync.aligned.m16n8k16.row.col.f32.bf16.bf16.f32 " \
                 "{%0,%1,%2,%3}, {%4,%5,%6,%7}, {%8,%9}, {%0,%1,%2,%3};" \
                 : "+f"((d)[0]), "+f"((d)[1]), "+f"((d)[2]), "+f"((d)[3]) \
                 : "r"((a)[0]), "r"((a)[1]), "r"((a)[2]), "r"((a)[3]), "r"(b0), "r"(b1))

__device__ __forceinline__ int chunk_t0(int c) { return 1 + c * L_BASE + (c < L_REM ? c : L_REM); }
__device__ __forceinline__ int chunk_len(int c) { return L_BASE + (c < L_REM ? 1 : 0); }

// ============================================================
__global__ void setup_kernel(const float* __restrict__ lambdas,
                             const float* __restrict__ log_transition) {
    int tid = threadIdx.x;
    for (int idx = tid; idx < NS * MD; idx += blockDim.x)
        g_loglam[idx] = logf(lambdas[idx]);
    if (tid < NS) {
        float s = 0.f;
        #pragma unroll
        for (int m = 0; m < MD; m++) s += lambdas[tid * MD + m];
        g_lamsum[tid] = s;
    }
    for (int idx = tid; idx < NS * NS; idx += blockDim.x)
        g_Alin[idx] = expf(log_transition[idx]);
    if (tid < 32) g_hist[tid] = 0u;
}

// ============================================================
__global__ void __launch_bounds__(256) pass0_kernel(const int* __restrict__ x) {
    __shared__ float sll[NS * MD];
    __shared__ float slam[NS];
    __shared__ unsigned int shist[32];
    int tid = threadIdx.x;
    for (int idx = tid; idx < NS * MD; idx += blockDim.x) sll[idx] = g_loglam[idx];
    if (tid < NS) slam[tid] = g_lamsum[tid];
    if (tid < 32) shist[tid] = 0u;
    __syncthreads();

    int warp = tid >> 5, lane = tid & 31;
    int t = blockIdx.x * 8 + warp;

    int4 xa = *(const int4*)&x[(size_t)t * MD];
    int4 xb = *(const int4*)&x[(size_t)t * MD + 4];
    int xv[8] = {xa.x, xa.y, xa.z, xa.w, xb.x, xb.y, xb.z, xb.w};
    if (lane < 8) atomicAdd(&shist[xv[lane] & 31], 1u);

    float e0 = -slam[lane], e1 = -slam[lane + 32];
    #pragma unroll
    for (int m = 0; m < 8; m++) {
        float xm = (float)xv[m];
        e0 = fmaf(xm, sll[lane * MD + m], e0);
        e1 = fmaf(xm, sll[(lane + 32) * MD + m], e1);
    }
    float mx = fmaxf(e0, e1);
    #pragma unroll
    for (int o = 16; o > 0; o >>= 1)
        mx = fmaxf(mx, __shfl_xor_sync(0xffffffffu, mx, o));
    g_w[(size_t)t * NS + lane]      = expf(e0 - mx);
    g_w[(size_t)t * NS + lane + 32] = expf(e1 - mx);
    if (lane == 0) g_maxlog[t] = mx;

    __syncthreads();
    if (tid < 32 && shist[tid]) atomicAdd(&g_hist[tid], shist[tid]);
}

// ============================================================
// Pass 1 (mma.sync bf16): one 64x64 chunk per CTA, 4 warps.
// Per step: D = A @ M via 32 HMMA/warp, scale rows by emission weights
// (lazy renormalization folded into next step's weights), bf16 back to SMEM.
// Warp w owns output columns [16w, 16w+16). A-fragments register-resident.
// ============================================================
__global__ void __launch_bounds__(128, 3) pass1_mma() {
    __shared__ __align__(1024) unsigned char sAraw[NS * 128];
    __shared__ __align__(1024) unsigned char sMraw[NS * 128];
    __shared__ float swf[2][NS];
    __shared__ float wmax[4];

    int tid = threadIdx.x, lane = tid & 31, wid = tid >> 5;
    int c = blockIdx.x;
    int t0 = chunk_t0(c);
    int nst = chunk_len(c);

    uint32_t sA = smem_u32(sAraw), sM = smem_u32(sMraw);

    // A -> bf16 swizzled SMEM
    for (int idx = tid; idx < NS * NS; idx += 128) {
        int i = idx >> 6, k = idx & 63;
        *(__nv_bfloat16*)(sAraw + SW128(i * 128 + k * 2)) = __float2bfloat16(g_Alin[idx]);
    }
    // M = identity
    for (int idx = tid; idx < (NS * 128) / 4; idx += 128)
        ((uint32_t*)sMraw)[idx] = 0u;
    __syncthreads();
    if (tid < NS) {
        *(__nv_bfloat16*)(sMraw + SW128(tid * 128 + tid * 2)) = __float2bfloat16(1.0f);
        swf[0][tid] = g_w[(size_t)t0 * NS + tid];
    }
    __syncthreads();

    // Register-resident A fragments: afr[mt][kt][0..3]
    uint32_t afr[4][4][4];
    {
        int g = lane >> 3, r = lane & 7;
        #pragma unroll
        for (int mt = 0; mt < 4; mt++)
            #pragma unroll
            for (int kt = 0; kt < 4; kt++) {
                int row = mt * 16 + (g & 1) * 8 + r;
                int col = kt * 16 + (g >> 1) * 8;
                uint32_t addr = sA + SW128(row * 128 + col * 2);
                LDSM_X4(afr[mt][kt][0], afr[mt][kt][1], afr[mt][kt][2], afr[mt][kt][3], addr);
            }
    }
    // Precomputed B ldmatrix addresses (one per k-tile; layout static across steps)
    uint32_t baddr[4];
    {
        int g = lane >> 3, r = lane & 7;
        #pragma unroll
        for (int kt = 0; kt < 4; kt++) {
            int row = kt * 16 + (g & 1) * 8 + r;
            int col = wid * 16 + (g >> 1) * 8;
            baddr[kt] = sM + SW128(row * 128 + col * 2);
        }
    }

    int r0b = lane >> 2;            // 0..7 (row within 8-group)
    int cpair = (lane & 3) * 2;     // 0,2,4,6 (col pair)
    float S = 0.f;
    int cur = 0;

    for (int step = 0; step < nst; step++) {
        bool last = (step == nst - 1);
        // prefetch next weights + this step's maxlog (hidden under MMA)
        float wn = 0.f;
        if (tid < NS && !last) wn = g_w[(size_t)(t0 + step + 1) * NS + tid];
        float ml = (tid == 0) ? g_maxlog[t0 + step] : 0.f;

        float acc[4][2][4];
        #pragma unroll
        for (int mt = 0; mt < 4; mt++)
            #pragma unroll
            for (int nt = 0; nt < 2; nt++)
                #pragma unroll
                for (int e = 0; e < 4; e++) acc[mt][nt][e] = 0.f;

        #pragma unroll
        for (int kt = 0; kt < 4; kt++) {
            uint32_t b0, b1, b2, b3;
            LDSM_X4_T(b0, b1, b2, b3, baddr[kt]);
            #pragma unroll
            for (int mt = 0; mt < 4; mt++) {
                MMA_BF16(acc[mt][0], afr[mt][kt], b0, b1);
                MMA_BF16(acc[mt][1], afr[mt][kt], b2, b3);
            }
        }
        __syncthreads();   // all warps done reading sM -> safe to overwrite

        float lmax = 0.f;
        #pragma unroll
        for (int mt = 0; mt < 4; mt++) {
            float w0 = swf[cur][mt * 16 + r0b];
            float w1 = swf[cur][mt * 16 + 8 + r0b];
            #pragma unroll
            for (int nt = 0; nt < 2; nt++) {
                int col = wid * 16 + nt * 8 + cpair;
                float v00 = acc[mt][nt][0] * w0, v01 = acc[mt][nt][1] * w0;
                float v10 = acc[mt][nt][2] * w1, v11 = acc[mt][nt][3] * w1;
                lmax = fmaxf(lmax, fmaxf(fmaxf(v00, v01), fmaxf(v10, v11)));
                uint32_t p0, p1;
                CVT_BF2(p0, v00, v01);
                CVT_BF2(p1, v10, v11);
                STS32(p0, sM + SW128((mt * 16 + r0b) * 128 + col * 2));
                STS32(p1, sM + SW128((mt * 16 + 8 + r0b) * 128 + col * 2));
                if (last) {
                    float* gd = g_M1 + (size_t)c * (NS * NS);
                    *(float2*)&gd[(mt * 16 + r0b) * NS + col]     = make_float2(v00, v01);
                    *(float2*)&gd[(mt * 16 + 8 + r0b) * NS + col] = make_float2(v10, v11);
                }
            }
        }
        #pragma unroll
        for (int o = 16; o > 0; o >>= 1)
            lmax = fmaxf(lmax, __shfl_xor_sync(0xffffffffu, lmax, o));
        if (lane == 0) wmax[wid] = lmax;
        __syncthreads();   // STS of new M + wmax visible

        float s = fmaxf(fmaxf(fmaxf(wmax[0], wmax[1]), fmaxf(wmax[2], wmax[3])), 1e-30f);
        if (!last) {
            if (tid < NS) swf[cur ^ 1][tid] = wn * (1.0f / s);
            if (tid == 0) S += ml + __logf(s);
        } else if (tid == 0) {
            S += ml;   // final matrix left un-normalized; downstream absorbs it
        }
        cur ^= 1;
    }
    if (tid == 0) g_S1[c] = S;
}

// ============================================================
// Triple-combine: R = M[3c+2] @ M[3c+1] @ M[3c]; store R in P-layout.
// ============================================================
#define CPAD 68
__global__ void __launch_bounds__(128) combine3_kernel() {
    __shared__ float sX[NS * CPAD];   // left operand, transposed on load: [k][out-row]
    __shared__ float sY[NS * CPAD];   // right operand / intermediate: [k][out-col]
    int c = blockIdx.x, tid = threadIdx.x;
    const float* Ma = g_M1 + (size_t)(3 * c) * NS * NS;
    const float* Mb = Ma + NS * NS;
    const float* Mc = Mb + NS * NS;

    int x0 = (tid >> 3) << 2;   // 4 output rows
    int y0 = (tid & 7) << 3;    // 8 output cols
    float acc[4][8];

    // ---- phase 1: T = Mb @ Ma ----
    for (int idx = tid; idx < NS * NS; idx += 128) {
        int i = idx >> 6, k = idx & 63;
        sX[k * CPAD + i] = Mb[idx];       // Mb^T
        sY[(idx >> 6) * CPAD + (idx & 63)] = Ma[idx];  // Ma direct [k][j]
    }
    __syncthreads();
    #pragma unroll
    for (int a = 0; a < 4; a++)
        #pragma unroll
        for (int b = 0; b < 8; b++) acc[a][b] = 0.f;
    #pragma unroll 8
    for (int k = 0; k < NS; k++) {
        float4 av = *(const float4*)&sX[k * CPAD + x0];
        float4 b0 = *(const float4*)&sY[k * CPAD + y0];
        float4 b1 = *(const float4*)&sY[k * CPAD + y0 + 4];
        float aa[4] = {av.x, av.y, av.z, av.w};
        float bb[8] = {b0.x, b0.y, b0.z, b0.w, b1.x, b1.y, b1.z, b1.w};
        #pragma unroll
        for (int a = 0; a < 4; a++)
            #pragma unroll
            for (int b = 0; b < 8; b++)
                acc[a][b] = fmaf(aa[a], bb[b], acc[a][b]);
    }
    __syncthreads();
    // write T into sY as [k][j] (T's row index becomes next phase's k)
    #pragma unroll
    for (int a = 0; a < 4; a++) {
        *(float4*)&sY[(x0 + a) * CPAD + y0] =
            make_float4(acc[a][0], acc[a][1], acc[a][2], acc[a][3]);
        *(float4*)&sY[(x0 + a) * CPAD + y0 + 4] =
            make_float4(acc[a][4], acc[a][5], acc[a][6], acc[a][7]);
    }
    // load Mc^T into sX
    for (int idx = tid; idx < NS * NS; idx += 128) {
        int i = idx >> 6, k = idx & 63;
        sX[k * CPAD + i] = Mc[idx];
    }
    __syncthreads();

    // ---- phase 2: R^T[j][i] = sum_k T[k][j] * Mc[i][k] ----
    // x-axis = j (from sY cols... note roles swap: av from sY, bv from sX)
    #pragma unroll
    for (int a = 0; a < 4; a++)
        #pragma unroll
        for (int b = 0; b < 8; b++) acc[a][b] = 0.f;
    #pragma unroll 8
    for (int k = 0; k < NS; k++) {
        float4 av = *(const float4*)&sY[k * CPAD + x0];      // T[k][j0..j0+4]
        float4 b0 = *(const float4*)&sX[k * CPAD + y0];      // Mc^T[k][i0..]
        float4 b1 = *(const float4*)&sX[k * CPAD + y0 + 4];
        float aa[4] = {av.x, av.y, av.z, av.w};
        float bb[8] = {b0.x, b0.y, b0.z, b0.w, b1.x, b1.y, b1.z, b1.w};
        #pragma unroll
        for (int a = 0; a < 4; a++)
            #pragma unroll
            for (int b = 0; b < 8; b++)
                acc[a][b] = fmaf(aa[a], bb[b], acc[a][b]);
    }
    float* dst = g_M3 + (size_t)c * NS * NS;   // P-layout [j][i]
    #pragma unroll
    for (int a = 0; a < 4; a++) {
        *(float4*)&dst[(x0 + a) * NS + y0] =
            make_float4(acc[a][0], acc[a][1], acc[a][2], acc[a][3]);
        *(float4*)&dst[(x0 + a) * NS + y0 + 4] =
            make_float4(acc[a][4], acc[a][5], acc[a][6], acc[a][7]);
    }
    if (tid == 0) g_S3[c] = g_S1[3 * c] + g_S1[3 * c + 1] + g_S1[3 * c + 2];
}

// ============================================================
// Pass 2: serial matvec over 148 combined chunks (P-layout).
// ============================================================
__global__ void __launch_bounds__(256) pass2_kernel(const int* __restrict__ x,
                                                    const float* __restrict__ priors,
                                                    float* __restrict__ out) {
    __shared__ float alpha[NS];
    __shared__ float part[256];
    __shared__ float anew[NS];
    __shared__ float evec[NS];
    __shared__ float wm2[2];
    int tid = threadIdx.x;
    int i = tid & 63, q = tid >> 6;

    if (tid < NS) {
        float e = priors[tid] - g_lamsum[tid];
        #pragma unroll
        for (int m = 0; m < MD; m++)
            e = fmaf((float)x[m], g_loglam[tid * MD + m], e);
        evec[tid] = e;
    }
    __syncthreads();
    if (tid < NS) {
        float m = evec[tid];
        #pragma unroll
        for (int o = 16; o > 0; o >>= 1)
            m = fmaxf(m, __shfl_xor_sync(0xffffffffu, m, o));
        if ((tid & 31) == 0) wm2[tid >> 5] = m;
    }
    __syncthreads();
    float m0 = fmaxf(wm2[0], wm2[1]);
    if (tid < NS) alpha[tid] = expf(evec[tid] - m0);
    double logscale = (double)m0;
    __syncthreads();

    float buf[2][16];
    #pragma unroll
    for (int r = 0; r < 16; r++)
        buf[0][r] = g_M3[(size_t)(q * 16 + r) * NS + i];
    int pp = 0;
    for (int c = 0; c < NCH3; c++) {
        if (c + 1 < NCH3) {
            #pragma unroll
            for (int r = 0; r < 16; r++)
                buf[pp ^ 1][r] = g_M3[(size_t)(c + 1) * (NS * NS) + (size_t)(q * 16 + r) * NS + i];
        }
        float partial = 0.f;
        #pragma unroll
        for (int r = 0; r < 16; r++)
            partial = fmaf(buf[pp][r], alpha[q * 16 + r], partial);
        part[tid] = partial;
        __syncthreads();
        if (tid < NS) {
            float a4 = part[tid] + part[tid + 64] + part[tid + 128] + part[tid + 192];
            anew[tid] = a4;
            float m = a4;
            #pragma unroll
            for (int o = 16; o > 0; o >>= 1)
                m = fmaxf(m, __shfl_xor_sync(0xffffffffu, m, o));
            if ((tid & 31) == 0) wm2[tid >> 5] = m;
        }
        __syncthreads();
        float s = fmaxf(fmaxf(wm2[0], wm2[1]), 1e-35f);
        if (tid == 0) logscale += (double)g_S3[c] + log((double)s);
        if (tid < NS) alpha[tid] = anew[tid] / s;
        __syncthreads();
        pp ^= 1;
    }

    if (tid == 0) {
        double sum = 0.0;
        for (int k = 0; k < NS; k++) sum += (double)alpha[k];
        double lgam = 0.0;
        for (int b = 0; b < 32; b++) {
            unsigned int cnt = g_hist[b];
            if (cnt) lgam += (double)cnt * lgamma((double)b + 1.0);
        }
        out[0] = (float)(logscale + log(sum) - lgam);
    }
}

// ============================================================
extern "C" void kernel_launch(void* const* d_in, const int* in_sizes, int n_in,
                              void* d_out, int out_size) {
    const int*   x              = (const int*)d_in[0];
    const float* lambdas        = (const float*)d_in[1];
    const float* log_transition = (const float*)d_in[2];
    const float* priors         = (const float*)d_in[3];
    float* out = (float*)d_out;

    setup_kernel<<<1, 256>>>(lambdas, log_transition);
    pass0_kernel<<<T_LEN / 8, 256>>>(x);
    pass1_mma<<<NCH1, 128>>>();
    combine3_kernel<<<NCH3, 128>>>();
    pass2_kernel<<<1, 256>>>(x, priors, out);
}

// round 5
// speedup vs baseline: 7.8136x; 1.1263x over previous
#include <cuda_runtime.h>
#include <cuda_bf16.h>
#include <math.h>
#include <stdint.h>

#define T_LEN 131072
#define NS 64
#define MD 8
#define NCH1 444          // pass1 chunks: 3 per SM * 148
#define NCH3 148          // after triple-combine
#define L_BASE 295        // 131071 = 444*295 + 91
#define L_REM 91          // first 91 chunks have length 296

// ---- static device scratch ----
__device__ float g_w[(size_t)T_LEN * NS];
__device__ float g_maxlog[T_LEN];
__device__ float g_loglam[NS * MD];
__device__ float g_lamsum[NS];
__device__ float g_Alin[NS * NS];
__device__ float g_M1[(size_t)NCH1 * NS * NS];   // natural layout: [c][i][j]
__device__ float g_M3[(size_t)NCH3 * NS * NS];   // P-layout: [c][j][i] = R[i][j]
__device__ float g_S1[NCH1];
__device__ float g_S3[NCH3];
__device__ unsigned int g_hist[32];

// ================= helpers =================
__device__ __forceinline__ uint32_t smem_u32(const void* p) {
    uint32_t a;
    asm("{ .reg .u64 t; cvta.to.shared.u64 t, %1; cvt.u32.u64 %0, t; }" : "=r"(a) : "l"(p));
    return a;
}
#define SW128(o) ((uint32_t)(o) ^ ((((uint32_t)(o)) >> 3) & 0x70u))
#define CVT_BF2(r, lo, hi) asm("cvt.rn.bf16x2.f32 %0, %1, %2;" : "=r"(r) : "f"(hi), "f"(lo))
#define STS32(v, a) asm volatile("st.shared.b32 [%0], %1;" :: "r"(a), "r"(v) : "memory")
#define LDSM_X4(r0, r1, r2, r3, a) \
    asm volatile("ldmatrix.sync.aligned.m8n8.x4.shared.b16 {%0,%1,%2,%3}, [%4];" \
                 : "=r"(r0), "=r"(r1), "=r"(r2), "=r"(r3) : "r"(a))
#define LDSM_X4_T(r0, r1, r2, r3, a) \
    asm volatile("ldmatrix.sync.aligned.m8n8.x4.trans.shared.b16 {%0,%1,%2,%3}, [%4];" \
                 : "=r"(r0), "=r"(r1), "=r"(r2), "=r"(r3) : "r"(a))
#define MMA_BF16(d, a, b0, b1) \
    asm volatile("mma.sync.aligned.m16n8k16.row.col.f32.bf16.bf16.f32 " \
                 "{%0,%1,%2,%3}, {%4,%5,%6,%7}, {%8,%9}, {%0,%1,%2,%3};" \
                 : "+f"((d)[0]), "+f"((d)[1]), "+f"((d)[2]), "+f"((d)[3]) \
                 : "r"((a)[0]), "r"((a)[1]), "r"((a)[2]), "r"((a)[3]), "r"(b0), "r"(b1))

__device__ __forceinline__ int chunk_t0(int c) { return 1 + c * L_BASE + (c < L_REM ? c : L_REM); }
__device__ __forceinline__ int chunk_len(int c) { return L_BASE + (c < L_REM ? 1 : 0); }

// ============================================================
__global__ void setup_kernel(const float* __restrict__ lambdas,
                             const float* __restrict__ log_transition) {
    int tid = threadIdx.x;
    for (int idx = tid; idx < NS * MD; idx += blockDim.x)
        g_loglam[idx] = logf(lambdas[idx]);
    if (tid < NS) {
        float s = 0.f;
        #pragma unroll
        for (int m = 0; m < MD; m++) s += lambdas[tid * MD + m];
        g_lamsum[tid] = s;
    }
    for (int idx = tid; idx < NS * NS; idx += blockDim.x)
        g_Alin[idx] = expf(log_transition[idx]);
    if (tid < 32) g_hist[tid] = 0u;
}

// ============================================================
__global__ void __launch_bounds__(256) pass0_kernel(const int* __restrict__ x) {
    __shared__ float sll[NS * MD];
    __shared__ float slam[NS];
    __shared__ unsigned int shist[32];
    int tid = threadIdx.x;
    for (int idx = tid; idx < NS * MD; idx += blockDim.x) sll[idx] = g_loglam[idx];
    if (tid < NS) slam[tid] = g_lamsum[tid];
    if (tid < 32) shist[tid] = 0u;
    __syncthreads();

    int warp = tid >> 5, lane = tid & 31;
    int t = blockIdx.x * 8 + warp;

    int4 xa = *(const int4*)&x[(size_t)t * MD];
    int4 xb = *(const int4*)&x[(size_t)t * MD + 4];
    int xv[8] = {xa.x, xa.y, xa.z, xa.w, xb.x, xb.y, xb.z, xb.w};
    if (lane < 8) atomicAdd(&shist[xv[lane] & 31], 1u);

    float e0 = -slam[lane], e1 = -slam[lane + 32];
    #pragma unroll
    for (int m = 0; m < 8; m++) {
        float xm = (float)xv[m];
        e0 = fmaf(xm, sll[lane * MD + m], e0);
        e1 = fmaf(xm, sll[(lane + 32) * MD + m], e1);
    }
    float mx = fmaxf(e0, e1);
    #pragma unroll
    for (int o = 16; o > 0; o >>= 1)
        mx = fmaxf(mx, __shfl_xor_sync(0xffffffffu, mx, o));
    g_w[(size_t)t * NS + lane]      = expf(e0 - mx);
    g_w[(size_t)t * NS + lane + 32] = expf(e1 - mx);
    if (lane == 0) g_maxlog[t] = mx;

    __syncthreads();
    if (tid < 32 && shist[tid]) atomicAdd(&g_hist[tid], shist[tid]);
}

// ============================================================
// Pass 1 (mma.sync bf16): one 64x64 chunk per CTA, 4 warps.
// Double-buffered M (ping-pong) -> 1 barrier per normal step.
// Renormalization every 8 steps + forced on the last step.
// ============================================================
#define RENORM_MASK 7
__global__ void __launch_bounds__(128, 3) pass1_mma() {
    __shared__ __align__(1024) unsigned char sAraw[NS * 128];
    __shared__ __align__(1024) unsigned char sMraw[2 * NS * 128];  // ping-pong tiles
    __shared__ float swf[2][NS];
    __shared__ float wmax[4];

    int tid = threadIdx.x, lane = tid & 31, wid = tid >> 5;
    int c = blockIdx.x;
    int t0 = chunk_t0(c);
    int nst = chunk_len(c);

    uint32_t sA = smem_u32(sAraw), sM = smem_u32(sMraw);

    // A -> bf16 swizzled SMEM
    for (int idx = tid; idx < NS * NS; idx += 128) {
        int i = idx >> 6, k = idx & 63;
        *(__nv_bfloat16*)(sAraw + SW128(i * 128 + k * 2)) = __float2bfloat16(g_Alin[idx]);
    }
    // tile 0 = identity
    for (int idx = tid; idx < (NS * 128) / 4; idx += 128)
        ((uint32_t*)sMraw)[idx] = 0u;
    __syncthreads();
    if (tid < NS) {
        *(__nv_bfloat16*)(sMraw + SW128(tid * 128 + tid * 2)) = __float2bfloat16(1.0f);
        swf[0][tid] = g_w[(size_t)t0 * NS + tid];
    }
    __syncthreads();

    // Register-resident A fragments
    uint32_t afr[4][4][4];
    {
        int g = lane >> 3, r = lane & 7;
        #pragma unroll
        for (int mt = 0; mt < 4; mt++)
            #pragma unroll
            for (int kt = 0; kt < 4; kt++) {
                int row = mt * 16 + (g & 1) * 8 + r;
                int col = kt * 16 + (g >> 1) * 8;
                LDSM_X4(afr[mt][kt][0], afr[mt][kt][1], afr[mt][kt][2], afr[mt][kt][3],
                        sA + SW128(row * 128 + col * 2));
            }
    }
    // B ldmatrix base addresses (tile 0; tile 1 = +8192)
    uint32_t baddr[4];
    {
        int g = lane >> 3, r = lane & 7;
        #pragma unroll
        for (int kt = 0; kt < 4; kt++) {
            int row = kt * 16 + (g & 1) * 8 + r;
            int col = wid * 16 + (g >> 1) * 8;
            baddr[kt] = sM + SW128(row * 128 + col * 2);
        }
    }

    int r0b = lane >> 2;            // 0..7
    int cpair = (lane & 3) * 2;     // 0,2,4,6
    float S = 0.f;

    for (int step = 0; step < nst; step++) {
        int cur = step & 1;
        uint32_t curoff = (uint32_t)cur << 13;
        bool last = (step == nst - 1);
        bool renorm = ((step & RENORM_MASK) == RENORM_MASK) || last;

        float wn = 0.f;
        if (tid < NS && !last) wn = g_w[(size_t)(t0 + step + 1) * NS + tid];
        float ml = (tid == 0) ? g_maxlog[t0 + step] : 0.f;

        float acc[4][2][4];
        #pragma unroll
        for (int mt = 0; mt < 4; mt++)
            #pragma unroll
            for (int nt = 0; nt < 2; nt++)
                #pragma unroll
                for (int e = 0; e < 4; e++) acc[mt][nt][e] = 0.f;

        #pragma unroll
        for (int kt = 0; kt < 4; kt++) {
            uint32_t b0, b1, b2, b3;
            LDSM_X4_T(b0, b1, b2, b3, baddr[kt] + curoff);
            #pragma unroll
            for (int mt = 0; mt < 4; mt++) {
                MMA_BF16(acc[mt][0], afr[mt][kt], b0, b1);
                MMA_BF16(acc[mt][1], afr[mt][kt], b2, b3);
            }
        }

        // scale rows by emission weights (in place)
        #pragma unroll
        for (int mt = 0; mt < 4; mt++) {
            float w0 = swf[cur][mt * 16 + r0b];
            float w1 = swf[cur][mt * 16 + 8 + r0b];
            #pragma unroll
            for (int nt = 0; nt < 2; nt++) {
                acc[mt][nt][0] *= w0; acc[mt][nt][1] *= w0;
                acc[mt][nt][2] *= w1; acc[mt][nt][3] *= w1;
            }
        }

        if (!last) {
            // write to the OTHER tile (no WAR hazard -> no pre-barrier)
            uint32_t dstb = sM + (curoff ^ 8192u);
            #pragma unroll
            for (int mt = 0; mt < 4; mt++) {
                #pragma unroll
                for (int nt = 0; nt < 2; nt++) {
                    int col = wid * 16 + nt * 8 + cpair;
                    uint32_t p0, p1;
                    CVT_BF2(p0, acc[mt][nt][0], acc[mt][nt][1]);
                    CVT_BF2(p1, acc[mt][nt][2], acc[mt][nt][3]);
                    STS32(p0, dstb + SW128((mt * 16 + r0b) * 128 + col * 2));
                    STS32(p1, dstb + SW128((mt * 16 + 8 + r0b) * 128 + col * 2));
                }
            }
        }

        if (renorm) {
            float lmax = 0.f;
            #pragma unroll
            for (int mt = 0; mt < 4; mt++)
                #pragma unroll
                for (int nt = 0; nt < 2; nt++)
                    #pragma unroll
                    for (int e = 0; e < 4; e++) lmax = fmaxf(lmax, acc[mt][nt][e]);
            #pragma unroll
            for (int o = 16; o > 0; o >>= 1)
                lmax = fmaxf(lmax, __shfl_xor_sync(0xffffffffu, lmax, o));
            if (lane == 0) wmax[wid] = lmax;
            __syncthreads();
            float s = fmaxf(fmaxf(fmaxf(wmax[0], wmax[1]), fmaxf(wmax[2], wmax[3])), 1e-30f);
            float inv = 1.0f / s;
            if (!last) {
                // fold 1/s into next step's weights (applied after next MMA)
                if (tid < NS) swf[cur ^ 1][tid] = wn * inv;
                if (tid == 0) S += ml + __logf(s);
            } else {
                // normalized final chunk matrix -> gmem (fp32)
                float* gd = g_M1 + (size_t)c * (NS * NS);
                #pragma unroll
                for (int mt = 0; mt < 4; mt++) {
                    #pragma unroll
                    for (int nt = 0; nt < 2; nt++) {
                        int col = wid * 16 + nt * 8 + cpair;
                        *(float2*)&gd[(mt * 16 + r0b) * NS + col] =
                            make_float2(acc[mt][nt][0] * inv, acc[mt][nt][1] * inv);
                        *(float2*)&gd[(mt * 16 + 8 + r0b) * NS + col] =
                            make_float2(acc[mt][nt][2] * inv, acc[mt][nt][3] * inv);
                    }
                }
                if (tid == 0) S += ml + __logf(s);
            }
        } else {
            if (tid < NS) swf[cur ^ 1][tid] = wn;
            if (tid == 0) S += ml;
        }
        __syncthreads();   // new M tile + swf visible for next step
    }
    if (tid == 0) g_S1[c] = S;
}

// ============================================================
// Triple-combine: R = M[3c+2] @ M[3c+1] @ M[3c]; store R in P-layout.
// 256 threads, 4x4 tiles, TWO smem tiles (fits 48KB static limit):
//   phase1: sX=Mb^T, sY=Ma -> T;  T overwrites sY;  Mc^T -> sX;  phase2.
// ============================================================
#define CPAD 68
__global__ void __launch_bounds__(256) combine3_kernel() {
    __shared__ float sX[NS * CPAD];
    __shared__ float sY[NS * CPAD];
    int c = blockIdx.x, tid = threadIdx.x;
    const float* Ma = g_M1 + (size_t)(3 * c) * NS * NS;
    const float* Mb = Ma + NS * NS;
    const float* Mc = Mb + NS * NS;

    for (int idx = tid; idx < NS * NS; idx += 256) {
        int i = idx >> 6, k = idx & 63;
        sX[k * CPAD + i] = Mb[idx];    // Mb^T
        sY[i * CPAD + k] = Ma[idx];    // Ma direct [row=k-dim][col=j]
    }
    __syncthreads();

    int x0 = (tid >> 4) << 2;   // 4 output rows
    int y0 = (tid & 15) << 2;   // 4 output cols
    float acc[4][4];

    // ---- phase 1: T = Mb @ Ma ----
    #pragma unroll
    for (int a = 0; a < 4; a++)
        #pragma unroll
        for (int b = 0; b < 4; b++) acc[a][b] = 0.f;
    #pragma unroll 8
    for (int k = 0; k < NS; k++) {
        float4 av = *(const float4*)&sX[k * CPAD + x0];
        float4 bv = *(const float4*)&sY[k * CPAD + y0];
        float aa[4] = {av.x, av.y, av.z, av.w};
        float bb[4] = {bv.x, bv.y, bv.z, bv.w};
        #pragma unroll
        for (int a = 0; a < 4; a++)
            #pragma unroll
            for (int b = 0; b < 4; b++)
                acc[a][b] = fmaf(aa[a], bb[b], acc[a][b]);
    }
    __syncthreads();   // done reading sX (Mb^T) and sY (Ma)

    // T -> sY as [row=k-of-phase2][col=j]; Mc^T -> sX
    #pragma unroll
    for (int a = 0; a < 4; a++)
        *(float4*)&sY[(x0 + a) * CPAD + y0] =
            make_float4(acc[a][0], acc[a][1], acc[a][2], acc[a][3]);
    for (int idx = tid; idx < NS * NS; idx += 256) {
        int i = idx >> 6, k = idx & 63;
        sX[k * CPAD + i] = Mc[idx];    // Mc^T
    }
    __syncthreads();

    // ---- phase 2: R^T[j][i] = sum_k T[k][j] * Mc[i][k]  (x-axis = j, y-axis = i)
    #pragma unroll
    for (int a = 0; a < 4; a++)
        #pragma unroll
        for (int b = 0; b < 4; b++) acc[a][b] = 0.f;
    #pragma unroll 8
    for (int k = 0; k < NS; k++) {
        float4 av = *(const float4*)&sY[k * CPAD + x0];   // T[k][j0..]
        float4 bv = *(const float4*)&sX[k * CPAD + y0];   // Mc^T[k][i0..]
        float aa[4] = {av.x, av.y, av.z, av.w};
        float bb[4] = {bv.x, bv.y, bv.z, bv.w};
        #pragma unroll
        for (int a = 0; a < 4; a++)
            #pragma unroll
            for (int b = 0; b < 4; b++)
                acc[a][b] = fmaf(aa[a], bb[b], acc[a][b]);
    }
    float* dst = g_M3 + (size_t)c * NS * NS;   // P-layout [j][i]
    #pragma unroll
    for (int a = 0; a < 4; a++)
        *(float4*)&dst[(x0 + a) * NS + y0] =
            make_float4(acc[a][0], acc[a][1], acc[a][2], acc[a][3]);
    if (tid == 0) g_S3[c] = g_S1[3 * c] + g_S1[3 * c + 1] + g_S1[3 * c + 2];
}

// ============================================================
// Pass 2: serial matvec over 148 combined chunks (P-layout).
// ============================================================
__global__ void __launch_bounds__(256) pass2_kernel(const int* __restrict__ x,
                                                    const float* __restrict__ priors,
                                                    float* __restrict__ out) {
    __shared__ float alpha[NS];
    __shared__ float part[256];
    __shared__ float anew[NS];
    __shared__ float evec[NS];
    __shared__ float wm2[2];
    int tid = threadIdx.x;
    int i = tid & 63, q = tid >> 6;

    if (tid < NS) {
        float e = priors[tid] - g_lamsum[tid];
        #pragma unroll
        for (int m = 0; m < MD; m++)
            e = fmaf((float)x[m], g_loglam[tid * MD + m], e);
        evec[tid] = e;
    }
    __syncthreads();
    if (tid < NS) {
        float m = evec[tid];
        #pragma unroll
        for (int o = 16; o > 0; o >>= 1)
            m = fmaxf(m, __shfl_xor_sync(0xffffffffu, m, o));
        if ((tid & 31) == 0) wm2[tid >> 5] = m;
    }
    __syncthreads();
    float m0 = fmaxf(wm2[0], wm2[1]);
    if (tid < NS) alpha[tid] = expf(evec[tid] - m0);
    double logscale = (double)m0;
    __syncthreads();

    float buf[2][16];
    #pragma unroll
    for (int r = 0; r < 16; r++)
        buf[0][r] = g_M3[(size_t)(q * 16 + r) * NS + i];
    int pp = 0;
    for (int c = 0; c < NCH3; c++) {
        if (c + 1 < NCH3) {
            #pragma unroll
            for (int r = 0; r < 16; r++)
                buf[pp ^ 1][r] = g_M3[(size_t)(c + 1) * (NS * NS) + (size_t)(q * 16 + r) * NS + i];
        }
        float partial = 0.f;
        #pragma unroll
        for (int r = 0; r < 16; r++)
            partial = fmaf(buf[pp][r], alpha[q * 16 + r], partial);
        part[tid] = partial;
        __syncthreads();
        if (tid < NS) {
            float a4 = part[tid] + part[tid + 64] + part[tid + 128] + part[tid + 192];
            anew[tid] = a4;
            float m = a4;
            #pragma unroll
            for (int o = 16; o > 0; o >>= 1)
                m = fmaxf(m, __shfl_xor_sync(0xffffffffu, m, o));
            if ((tid & 31) == 0) wm2[tid >> 5] = m;
        }
        __syncthreads();
        float s = fmaxf(fmaxf(wm2[0], wm2[1]), 1e-35f);
        if (tid == 0) logscale += (double)g_S3[c] + log((double)s);
        if (tid < NS) alpha[tid] = anew[tid] / s;
        __syncthreads();
        pp ^= 1;
    }

    if (tid == 0) {
        double sum = 0.0;
        for (int k = 0; k < NS; k++) sum += (double)alpha[k];
        double lgam = 0.0;
        for (int b = 0; b < 32; b++) {
            unsigned int cnt = g_hist[b];
            if (cnt) lgam += (double)cnt * lgamma((double)b + 1.0);
        }
        out[0] = (float)(logscale + log(sum) - lgam);
    }
}

// ============================================================
extern "C" void kernel_launch(void* const* d_in, const int* in_sizes, int n_in,
                              void* d_out, int out_size) {
    const int*   x              = (const int*)d_in[0];
    const float* lambdas        = (const float*)d_in[1];
    const float* log_transition = (const float*)d_in[2];
    const float* priors         = (const float*)d_in[3];
    float* out = (float*)d_out;

    setup_kernel<<<1, 256>>>(lambdas, log_transition);
    pass0_kernel<<<T_LEN / 8, 256>>>(x);
    pass1_mma<<<NCH1, 128>>>();
    combine3_kernel<<<NCH3, 256>>>();
    pass2_kernel<<<1, 256>>>(x, priors, out);
}